// round 9
// baseline (speedup 1.0000x reference)
#include <cuda_runtime.h>
#include <cuda_fp16.h>
#include <cstddef>
#include <cstdint>

// Problem constants
constexpr int N_  = 25000;   // nodes
constexpr int E_  = 100000;  // edges
constexpr int H_  = 32;      // hidden
constexpr int NC_ = 8000;    // cliques
constexpr int A_  = 50000;   // node2clique assignments
constexpr int EC_ = 24000;   // clique edges
constexpr int L_  = 2;       // layers
constexpr int HH_ = 1024;    // H*H

// Scratch (device globals; no runtime allocation allowed)
// Y stored fp16, PLAIN row-major: Yh[n*1024 + k*32 + o]
__device__ __half g_Yh[(size_t)N_ * HH_];
__device__ float g_z[N_ * H_];
__device__ float g_x[N_ * H_];
__device__ float g_x2[N_ * H_];
__device__ float g_c[NC_ * H_];
__device__ float g_c2[NC_ * H_];
__device__ float g_agg[N_ * H_];
__device__ float g_m[N_ * H_];
__device__ float g_cntE[N_];
__device__ float g_cntCE[NC_];
__device__ float g_cntAc[NC_];
__device__ float g_cntAn[N_];
// CSR (rebuilt each call; index sets are call-invariant inputs)
__device__ int   g_cntSN[N_];
__device__ int   g_cntSC[NC_];
__device__ int   g_rpN[N_ + 1];
__device__ int   g_rpC[NC_ + 1];
__device__ int   g_curN[N_];
__device__ int   g_curC[NC_];
__device__ int   g_dstsN[E_];
__device__ int   g_dstsC[EC_];
__device__ float g_efsN[(size_t)E_ * 8];
__device__ float g_efsC[(size_t)EC_ * 8];

static __device__ __forceinline__ uint32_t smemu32(const void* p) {
    return (uint32_t)__cvta_generic_to_shared(p);
}

// ---------------------------------------------------------------------------
__global__ void k_zero_all(float* __restrict__ cntE, float* __restrict__ cntCE,
                           float* __restrict__ cntAc, float* __restrict__ cntAn,
                           float* __restrict__ agg,
                           int* __restrict__ cntSN, int* __restrict__ cntSC)
{
    int i = blockIdx.x * blockDim.x + threadIdx.x;
    int stride = gridDim.x * blockDim.x;
    for (int j = i; j < N_; j += stride) { cntE[j] = 0.f; cntAn[j] = 0.f; cntSN[j] = 0; }
    for (int j = i; j < NC_; j += stride) { cntCE[j] = 0.f; cntAc[j] = 0.f; cntSC[j] = 0; }
    for (int j = i; j < N_ * H_; j += stride) agg[j] = 0.f;
}

__global__ void k_count_all(const int* __restrict__ esrc, const int* __restrict__ edst,
                            const int* __restrict__ csrc, const int* __restrict__ cedst,
                            const int* __restrict__ nid, const int* __restrict__ cid,
                            float* __restrict__ cntE, float* __restrict__ cntCE,
                            float* __restrict__ cntAc, float* __restrict__ cntAn,
                            int* __restrict__ cntSN, int* __restrict__ cntSC)
{
    int i = blockIdx.x * blockDim.x + threadIdx.x;
    int stride = gridDim.x * blockDim.x;
    for (int j = i; j < E_; j += stride) {
        atomicAdd(&cntE[edst[j]], 1.f);
        atomicAdd(&cntSN[esrc[j]], 1);
    }
    for (int j = i; j < EC_; j += stride) {
        atomicAdd(&cntCE[cedst[j]], 1.f);
        atomicAdd(&cntSC[csrc[j]], 1);
    }
    for (int j = i; j < A_; j += stride) {
        atomicAdd(&cntAc[cid[j]], 1.f);
        atomicAdd(&cntAn[nid[j]], 1.f);
    }
}

// Exclusive scan of cnt[0..n) -> rowptr[0..n], also writes cur = rowptr[0..n).
// One block of 1024 threads.
__global__ __launch_bounds__(1024) void k_scan(
    const int* __restrict__ cnt, int* __restrict__ rowptr,
    int* __restrict__ cur, int n)
{
    __shared__ int part[1024];
    int tid = threadIdx.x;
    int chunk = (n + 1023) >> 10;
    int lo = tid * chunk;
    int hi = lo + chunk; if (hi > n) hi = n; if (lo > n) lo = n;
    int s = 0;
    for (int i = lo; i < hi; i++) s += cnt[i];
    part[tid] = s;
    __syncthreads();
    for (int d = 1; d < 1024; d <<= 1) {
        int t = (tid >= d) ? part[tid - d] : 0;
        __syncthreads();
        part[tid] += t;
        __syncthreads();
    }
    int run = part[tid] - s;   // exclusive prefix of this thread's chunk
    for (int i = lo; i < hi; i++) {
        rowptr[i] = run; cur[i] = run; run += cnt[i];
    }
    if (tid == 1023) rowptr[n] = part[1023];
}

// Sort edges by src via atomic cursors; pre-gather ef + dst into sorted order.
__global__ void k_fill(const int* __restrict__ esrc, const int* __restrict__ edst,
                       const float* __restrict__ ef,
                       const int* __restrict__ csrc, const int* __restrict__ cedst,
                       const float* __restrict__ cef,
                       int* __restrict__ curN, int* __restrict__ curC,
                       int* __restrict__ dstsN, int* __restrict__ dstsC,
                       float* __restrict__ efsN, float* __restrict__ efsC)
{
    int i = blockIdx.x * blockDim.x + threadIdx.x;
    int stride = gridDim.x * blockDim.x;
    for (int e = i; e < E_; e += stride) {
        int j = atomicAdd(&curN[esrc[e]], 1);
        dstsN[j] = edst[e];
        float4 a = ((const float4*)ef)[e * 2];
        float4 b = ((const float4*)ef)[e * 2 + 1];
        ((float4*)efsN)[j * 2] = a;
        ((float4*)efsN)[j * 2 + 1] = b;
    }
    for (int e = i; e < EC_; e += stride) {
        int j = atomicAdd(&curC[csrc[e]], 1);
        dstsC[j] = cedst[e];
        float4 a = ((const float4*)cef)[e * 2];
        float4 b = ((const float4*)cef)[e * 2 + 1];
        ((float4*)efsC)[j * 2] = a;
        ((float4*)efsC)[j * 2 + 1] = b;
    }
}

// ---------------------------------------------------------------------------
// Tensor-core Y GEMM + folded z.
// W2 layout: W2[k*1024 + i*32 + o]; contraction index is i (middle). Staged
// permuted: W2h[i][k*32+o]. b2[i*32+o] staged as cols [1024,1056).
// Y fp16 row-major; z fp32 (computed by warps 0..3 as one extra n-tile each).
constexpr int W2S = 1064;          // padded fp16 row stride (2128B % 128 = 80 -> 8 distinct banks)
constexpr int XS  = 40;            // padded fp16 row stride for x tile
constexpr int SMEM_YTC = (32 * W2S + 64 * XS) * 2;

__global__ __launch_bounds__(256) void k_Y_tc(
    const float* __restrict__ x, const float* __restrict__ W2,
    const float* __restrict__ b2,
    __half* __restrict__ Yh, float* __restrict__ z, int rows)
{
    extern __shared__ __half smh[];
    __half* W2h = smh;             // [i=32][W2S]
    __half* xh  = smh + 32 * W2S;  // [64][XS]

    int tid = threadIdx.x, lane = tid & 31, w = tid >> 5;

    // Convert + PERMUTE W2 fp32 -> fp16 smem
    for (int idx = tid; idx < 8192; idx += 256) {
        float4 v = ((const float4*)W2)[idx];
        int g = idx * 4;
        int k = g >> 10, rem = g & 1023;
        int i = rem >> 5, o = rem & 31;
        __half2* dst = (__half2*)&W2h[i * W2S + k * 32 + o];
        dst[0] = __floats2half2_rn(v.x, v.y);
        dst[1] = __floats2half2_rn(v.z, v.w);
    }
    // b2 -> cols [1024,1056)
    {
        float4 vb = ((const float4*)b2)[tid];
        int g = tid * 4;
        int i = g >> 5, o = g & 31;
        __half2* dst = (__half2*)&W2h[i * W2S + 1024 + o];
        dst[0] = __floats2half2_rn(vb.x, vb.y);
        dst[1] = __floats2half2_rn(vb.z, vb.w);
    }
    // x tile -> fp16 smem (zero-padded)
    int n0 = blockIdx.x * 64;
    for (int i = tid; i < 64 * 32; i += 256) {
        int r = i >> 5, cc = i & 31;
        float v = (n0 + r < rows) ? x[(size_t)(n0 + r) * 32 + cc] : 0.f;
        xh[r * XS + cc] = __float2half_rn(v);
    }
    __syncthreads();

    // A fragments: 4 m-tiles x 2 k-steps
    uint32_t A[4][2][4];
    #pragma unroll
    for (int m = 0; m < 4; m++) {
        #pragma unroll
        for (int ks = 0; ks < 2; ks++) {
            uint32_t addr = smemu32(&xh[(m * 16 + (lane & 15)) * XS + ks * 16 + (lane >> 4) * 8]);
            asm volatile("ldmatrix.sync.aligned.m8n8.x4.shared.b16 {%0,%1,%2,%3}, [%4];"
                         : "=r"(A[m][ks][0]), "=r"(A[m][ks][1]),
                           "=r"(A[m][ks][2]), "=r"(A[m][ks][3])
                         : "r"(addr));
        }
    }

    int nb0 = w * 128;
    __half2* Y2 = (__half2*)Yh;
    #pragma unroll 4
    for (int n = 0; n < 16; n++) {
        int nb = nb0 + n * 8;
        uint32_t B[2][2];
        #pragma unroll
        for (int ks = 0; ks < 2; ks++) {
            uint32_t addr = smemu32(&W2h[(ks * 16 + (lane & 15)) * W2S + nb]);
            asm volatile("ldmatrix.sync.aligned.m8n8.x2.trans.shared.b16 {%0,%1}, [%2];"
                         : "=r"(B[ks][0]), "=r"(B[ks][1]) : "r"(addr));
        }
        #pragma unroll
        for (int m = 0; m < 4; m++) {
            float c0 = 0.f, c1 = 0.f, c2 = 0.f, c3 = 0.f;
            asm volatile(
                "mma.sync.aligned.m16n8k16.row.col.f32.f16.f16.f32 "
                "{%0,%1,%2,%3}, {%4,%5,%6,%7}, {%8,%9}, {%0,%1,%2,%3};"
                : "+f"(c0), "+f"(c1), "+f"(c2), "+f"(c3)
                : "r"(A[m][0][0]), "r"(A[m][0][1]), "r"(A[m][0][2]), "r"(A[m][0][3]),
                  "r"(B[0][0]), "r"(B[0][1]));
            asm volatile(
                "mma.sync.aligned.m16n8k16.row.col.f32.f16.f16.f32 "
                "{%0,%1,%2,%3}, {%4,%5,%6,%7}, {%8,%9}, {%0,%1,%2,%3};"
                : "+f"(c0), "+f"(c1), "+f"(c2), "+f"(c3)
                : "r"(A[m][1][0]), "r"(A[m][1][1]), "r"(A[m][1][2]), "r"(A[m][1][3]),
                  "r"(B[1][0]), "r"(B[1][1]));
            int r0 = n0 + m * 16 + (lane >> 2);
            int colh = (nb >> 1) + (lane & 3);
            if (r0 < rows)
                Y2[(size_t)r0 * 512 + colh] = __floats2half2_rn(c0, c1);
            if (r0 + 8 < rows)
                Y2[(size_t)(r0 + 8) * 512 + colh] = __floats2half2_rn(c2, c3);
        }
    }

    // z tile: warps 0..3, B cols [1024 + w*8, +8)
    if (w < 4) {
        int nb = 1024 + w * 8;
        uint32_t B[2][2];
        #pragma unroll
        for (int ks = 0; ks < 2; ks++) {
            uint32_t addr = smemu32(&W2h[(ks * 16 + (lane & 15)) * W2S + nb]);
            asm volatile("ldmatrix.sync.aligned.m8n8.x2.trans.shared.b16 {%0,%1}, [%2];"
                         : "=r"(B[ks][0]), "=r"(B[ks][1]) : "r"(addr));
        }
        #pragma unroll
        for (int m = 0; m < 4; m++) {
            float c0 = 0.f, c1 = 0.f, c2 = 0.f, c3 = 0.f;
            asm volatile(
                "mma.sync.aligned.m16n8k16.row.col.f32.f16.f16.f32 "
                "{%0,%1,%2,%3}, {%4,%5,%6,%7}, {%8,%9}, {%0,%1,%2,%3};"
                : "+f"(c0), "+f"(c1), "+f"(c2), "+f"(c3)
                : "r"(A[m][0][0]), "r"(A[m][0][1]), "r"(A[m][0][2]), "r"(A[m][0][3]),
                  "r"(B[0][0]), "r"(B[0][1]));
            asm volatile(
                "mma.sync.aligned.m16n8k16.row.col.f32.f16.f16.f32 "
                "{%0,%1,%2,%3}, {%4,%5,%6,%7}, {%8,%9}, {%0,%1,%2,%3};"
                : "+f"(c0), "+f"(c1), "+f"(c2), "+f"(c3)
                : "r"(A[m][1][0]), "r"(A[m][1][1]), "r"(A[m][1][2]), "r"(A[m][1][3]),
                  "r"(B[1][0]), "r"(B[1][1]));
            int r0 = n0 + m * 16 + (lane >> 2);
            int col = w * 8 + (lane & 3) * 2;
            if (r0 < rows)
                *(float2*)&z[(size_t)r0 * 32 + col] = make_float2(c0, c1);
            if (r0 + 8 < rows)
                *(float2*)&z[(size_t)(r0 + 8) * 32 + col] = make_float2(c2, c3);
        }
    }
}

// ---------------------------------------------------------------------------
// CSR edge kernel: one warp per SOURCE node. Y row cached in registers,
// reused for all outgoing edges. Lane (p=lane>>4, q=lane&15) holds
// (k=2it+p, o=2q/2q+1) tiles; shfl_xor(16) combines; lane outputs o=2q+p.
__global__ __launch_bounds__(256) void k_edge_csr(
    const int* __restrict__ rowptr, const int* __restrict__ dsts,
    const float* __restrict__ efs,
    const float* __restrict__ w1, const float* __restrict__ b1,
    const __half* __restrict__ Yh, const float* __restrict__ z,
    float* __restrict__ agg, int nsrc)
{
    __shared__ float w1s[8 * 32];
    __shared__ float b1s[32];
    int tid = threadIdx.x;
    if (tid < 256) w1s[tid] = w1[tid];
    if (tid < 32)  b1s[tid] = b1[tid];
    __syncthreads();

    int lane = tid & 31;
    int s = blockIdx.x * 8 + (tid >> 5);
    if (s >= nsrc) return;
    int j0 = rowptr[s], j1 = rowptr[s + 1];
    if (j0 == j1) return;

    const __half2* Yr2 = (const __half2*)&Yh[(size_t)s * 1024];
    float2 v[16];
    #pragma unroll
    for (int it = 0; it < 16; it++)
        v[it] = __half22float2(Yr2[it * 32 + lane]);

    int p = lane >> 4, q = lane & 15, o = 2 * q + p;
    float zo = z[(size_t)s * 32 + o];

    for (int j = j0; j < j1; j++) {
        const float* efe = &efs[(size_t)j * 8];
        float h = b1s[lane];
        #pragma unroll
        for (int i2 = 0; i2 < 8; i2++) h += efe[i2] * w1s[i2 * 32 + lane];
        h = fmaxf(h, 0.f);

        float ax = 0.f, ay = 0.f;
        #pragma unroll
        for (int it = 0; it < 16; it++) {
            float hk = __shfl_sync(0xffffffffu, h, 2 * it + p);
            ax += hk * v[it].x;
            ay += hk * v[it].y;
        }
        ax += __shfl_xor_sync(0xffffffffu, ax, 16);
        ay += __shfl_xor_sync(0xffffffffu, ay, 16);
        float val = (p ? ay : ax) + zo;
        atomicAdd(&agg[(size_t)dsts[j] * 32 + o], val);
    }
}

// Fused: out = relu(agg/cnt + xin @ rw + rb) ; mout = out @ lw + lb
// Clears agg (consume-and-clear). One warp per row.
__global__ __launch_bounds__(256) void k_convlin(
    const float* __restrict__ xin, float* __restrict__ agg,
    const float* __restrict__ cnt,
    const float* __restrict__ rw, const float* __restrict__ rb,
    const float* __restrict__ lw, const float* __restrict__ lb,
    float* __restrict__ out, float* __restrict__ mout, int rows)
{
    __shared__ float rws[1024], lws[1024];
    __shared__ float rbs[32], lbs[32];
    int tid = threadIdx.x;
    for (int i = tid; i < 1024; i += 256) { rws[i] = rw[i]; lws[i] = lw[i]; }
    if (tid < 32) { rbs[tid] = rb[tid]; lbs[tid] = lb[tid]; }
    __syncthreads();

    int lane = tid & 31;
    int n = blockIdx.x * 8 + (tid >> 5);
    if (n >= rows) return;

    size_t base = (size_t)n * 32 + lane;
    float xr = xin[base];
    float acc = rbs[lane];
    #pragma unroll
    for (int i = 0; i < 32; i++)
        acc += __shfl_sync(0xffffffffu, xr, i) * rws[i * 32 + lane];
    float inv = 1.f / fmaxf(cnt[n], 1.f);
    acc += agg[base] * inv;
    agg[base] = 0.f;
    float o = fmaxf(acc, 0.f);
    out[base] = o;

    float macc = lbs[lane];
    #pragma unroll
    for (int i = 0; i < 32; i++)
        macc += __shfl_sync(0xffffffffu, o, i) * lws[i * 32 + lane];
    mout[base] = macc;
}

// One warp per assignment: agg[idx_out[a]] += m[idx_in[a]]
__global__ __launch_bounds__(256) void k_scatter(
    const int* __restrict__ idx_in, const int* __restrict__ idx_out,
    const float* __restrict__ m, float* __restrict__ agg, int n)
{
    int lane = threadIdx.x & 31;
    int a = blockIdx.x * 8 + (threadIdx.x >> 5);
    if (a >= n) return;
    atomicAdd(&agg[(size_t)idx_out[a] * 32 + lane],
              m[(size_t)idx_in[a] * 32 + lane]);
}

// out = base + agg/max(cnt,1); clears agg.
__global__ void k_resid(
    const float* __restrict__ base, float* __restrict__ agg,
    const float* __restrict__ cnt, float* __restrict__ out, int rows)
{
    int i = blockIdx.x * blockDim.x + threadIdx.x;
    if (i >= rows * 32) return;
    int n = i >> 5;
    out[i] = base[i] + agg[i] / fmaxf(cnt[n], 1.f);
    agg[i] = 0.f;
}

// ---------------------------------------------------------------------------
static inline int cdiv(int a, int b) { return (a + b - 1) / b; }

extern "C" void kernel_launch(void* const* d_in, const int* in_sizes, int n_in,
                              void* d_out, int out_size)
{
    const float* node_features   = (const float*)d_in[0];
    const int*   edge_index      = (const int*)d_in[1];
    const float* edge_features   = (const float*)d_in[2];
    const float* clique_features = (const float*)d_in[3];
    const int*   n2c_index       = (const int*)d_in[4];   // [2, A]: nid, cid
    const int*   cedge_index     = (const int*)d_in[5];
    const float* cedge_features  = (const float*)d_in[6];
    const float* nn1_w  = (const float*)d_in[7];
    const float* nn1_b  = (const float*)d_in[8];
    const float* nn2_w  = (const float*)d_in[9];
    const float* nn2_b  = (const float*)d_in[10];
    const float* root_w = (const float*)d_in[11];
    const float* root_b = (const float*)d_in[12];
    const float* n2c_w  = (const float*)d_in[13];
    const float* n2c_b  = (const float*)d_in[14];
    const float* cnn1_w = (const float*)d_in[15];
    const float* cnn1_b = (const float*)d_in[16];
    const float* cnn2_w = (const float*)d_in[17];
    const float* cnn2_b = (const float*)d_in[18];
    const float* croot_w = (const float*)d_in[19];
    const float* croot_b = (const float*)d_in[20];
    const float* c2n_w  = (const float*)d_in[21];
    const float* c2n_b  = (const float*)d_in[22];

    float *z, *x, *x2, *c, *c2, *agg, *m, *cntE, *cntCE, *cntAc, *cntAn;
    __half* Yh;
    int *cntSN, *cntSC, *rpN, *rpC, *curN, *curC, *dstsN, *dstsC;
    float *efsN, *efsC;
    cudaGetSymbolAddress((void**)&Yh, g_Yh);
    cudaGetSymbolAddress((void**)&z, g_z);
    cudaGetSymbolAddress((void**)&x, g_x);
    cudaGetSymbolAddress((void**)&x2, g_x2);
    cudaGetSymbolAddress((void**)&c, g_c);
    cudaGetSymbolAddress((void**)&c2, g_c2);
    cudaGetSymbolAddress((void**)&agg, g_agg);
    cudaGetSymbolAddress((void**)&m, g_m);
    cudaGetSymbolAddress((void**)&cntE, g_cntE);
    cudaGetSymbolAddress((void**)&cntCE, g_cntCE);
    cudaGetSymbolAddress((void**)&cntAc, g_cntAc);
    cudaGetSymbolAddress((void**)&cntAn, g_cntAn);
    cudaGetSymbolAddress((void**)&cntSN, g_cntSN);
    cudaGetSymbolAddress((void**)&cntSC, g_cntSC);
    cudaGetSymbolAddress((void**)&rpN, g_rpN);
    cudaGetSymbolAddress((void**)&rpC, g_rpC);
    cudaGetSymbolAddress((void**)&curN, g_curN);
    cudaGetSymbolAddress((void**)&curC, g_curC);
    cudaGetSymbolAddress((void**)&dstsN, g_dstsN);
    cudaGetSymbolAddress((void**)&dstsC, g_dstsC);
    cudaGetSymbolAddress((void**)&efsN, g_efsN);
    cudaGetSymbolAddress((void**)&efsC, g_efsC);

    float* out_x = (float*)d_out;                       // [N, H]
    float* out_c = (float*)d_out + (size_t)N_ * H_;     // [NC, H]

    cudaFuncSetAttribute(k_Y_tc, cudaFuncAttributeMaxDynamicSharedMemorySize, SMEM_YTC);

    // Setup: counts + CSR build
    k_zero_all<<<400, 256>>>(cntE, cntCE, cntAc, cntAn, agg, cntSN, cntSC);
    k_count_all<<<400, 256>>>(edge_index, edge_index + E_,
                              cedge_index, cedge_index + EC_,
                              n2c_index, n2c_index + A_,
                              cntE, cntCE, cntAc, cntAn, cntSN, cntSC);
    k_scan<<<1, 1024>>>(cntSN, rpN, curN, N_);
    k_scan<<<1, 1024>>>(cntSC, rpC, curC, NC_);
    k_fill<<<400, 256>>>(edge_index, edge_index + E_, edge_features,
                         cedge_index, cedge_index + EC_, cedge_features,
                         curN, curC, dstsN, dstsC, efsN, efsC);

    for (int l = 0; l < L_; l++) {
        const float* xin = (l == 0) ? node_features : x;
        const float* cin = (l == 0) ? clique_features : c;
        float* xout = (l == L_ - 1) ? out_x : x;
        float* cout = (l == L_ - 1) ? out_c : c;

        // ---- node NNConv + fused Node2Clique projection ----
        k_Y_tc<<<cdiv(N_, 64), 256, SMEM_YTC>>>(xin, nn2_w + (size_t)l * 32768,
                                                nn2_b + (size_t)l * 1024, Yh, z, N_);
        k_edge_csr<<<cdiv(N_, 8), 256>>>(rpN, dstsN, efsN,
                                         nn1_w + (size_t)l * 256, nn1_b + (size_t)l * 32,
                                         Yh, z, agg, N_);
        k_convlin<<<cdiv(N_, 8), 256>>>(xin, agg, cntE,
                                        root_w + (size_t)l * 1024, root_b + (size_t)l * 32,
                                        n2c_w + (size_t)l * 1024, n2c_b + (size_t)l * 32,
                                        x2, m, N_);
        k_scatter<<<cdiv(A_, 8), 256>>>(n2c_index, n2c_index + A_, m, agg, A_);
        k_resid<<<cdiv(NC_ * 32, 256), 256>>>(cin, agg, cntAc, c2, NC_);

        // ---- clique NNConv + fused Clique2Node projection ----
        k_Y_tc<<<cdiv(NC_, 64), 256, SMEM_YTC>>>(c2, cnn2_w + (size_t)l * 32768,
                                                 cnn2_b + (size_t)l * 1024, Yh, z, NC_);
        k_edge_csr<<<cdiv(NC_, 8), 256>>>(rpC, dstsC, efsC,
                                          cnn1_w + (size_t)l * 256, cnn1_b + (size_t)l * 32,
                                          Yh, z, agg, NC_);
        k_convlin<<<cdiv(NC_, 8), 256>>>(c2, agg, cntCE,
                                         croot_w + (size_t)l * 1024, croot_b + (size_t)l * 32,
                                         c2n_w + (size_t)l * 1024, c2n_b + (size_t)l * 32,
                                         cout, m, NC_);
        k_scatter<<<cdiv(A_, 8), 256>>>(n2c_index + A_, n2c_index, m, agg, A_);
        k_resid<<<cdiv(N_ * 32, 256), 256>>>(x2, agg, cntAn, xout, N_);
    }
}

// round 10
// speedup vs baseline: 1.1966x; 1.1966x over previous
#include <cuda_runtime.h>
#include <cuda_fp16.h>
#include <cstddef>
#include <cstdint>

// Problem constants
constexpr int N_  = 25000;   // nodes
constexpr int E_  = 100000;  // edges
constexpr int H_  = 32;      // hidden
constexpr int NC_ = 8000;    // cliques
constexpr int A_  = 50000;   // node2clique assignments
constexpr int EC_ = 24000;   // clique edges
constexpr int L_  = 2;       // layers
constexpr int HH_ = 1024;    // H*H

// Scratch (device globals; no runtime allocation allowed)
// Y stored fp16, PLAIN row-major: Yh[n*1024 + k*32 + o]
__device__ __half g_Yh[(size_t)N_ * HH_];
__device__ float g_z[N_ * H_];
__device__ float g_x[N_ * H_];
__device__ float g_x2[N_ * H_];
__device__ float g_c[NC_ * H_];
__device__ float g_c2[NC_ * H_];
__device__ float g_agg[N_ * H_];
__device__ float g_m[N_ * H_];
__device__ float g_cntE[N_];
__device__ float g_cntCE[NC_];
__device__ float g_cntAc[NC_];
__device__ float g_cntAn[N_];

static __device__ __forceinline__ uint32_t smemu32(const void* p) {
    return (uint32_t)__cvta_generic_to_shared(p);
}

// ---------------------------------------------------------------------------
__global__ void k_zero_all(float* __restrict__ cntE, float* __restrict__ cntCE,
                           float* __restrict__ cntAc, float* __restrict__ cntAn,
                           float* __restrict__ agg)
{
    int i = blockIdx.x * blockDim.x + threadIdx.x;
    int stride = gridDim.x * blockDim.x;
    for (int j = i; j < N_; j += stride) { cntE[j] = 0.f; cntAn[j] = 0.f; }
    for (int j = i; j < NC_; j += stride) { cntCE[j] = 0.f; cntAc[j] = 0.f; }
    for (int j = i; j < N_ * H_; j += stride) agg[j] = 0.f;
}

__global__ void k_count_all(const int* __restrict__ edst, const int* __restrict__ cedst,
                            const int* __restrict__ nid, const int* __restrict__ cid,
                            float* __restrict__ cntE, float* __restrict__ cntCE,
                            float* __restrict__ cntAc, float* __restrict__ cntAn)
{
    constexpr int T0 = E_, T1 = E_ + EC_, T2 = E_ + EC_ + A_, T3 = E_ + EC_ + A_ + A_;
    int i = blockIdx.x * blockDim.x + threadIdx.x;
    int stride = gridDim.x * blockDim.x;
    for (int j = i; j < T3; j += stride) {
        if (j < T0)      atomicAdd(&cntE[edst[j]], 1.f);
        else if (j < T1) atomicAdd(&cntCE[cedst[j - T0]], 1.f);
        else if (j < T2) atomicAdd(&cntAc[cid[j - T1]], 1.f);
        else             atomicAdd(&cntAn[nid[j - T2]], 1.f);
    }
}

// ---------------------------------------------------------------------------
// Tensor-core Y GEMM + folded z.
// W2 layout: W2[k*1024 + i*32 + o]; contraction index is i (middle). Staged
// permuted: W2h[i][k*32+o]. b2[i*32+o] staged as cols [1024,1056).
// Y fp16 row-major; z fp32 (computed by warps 0..3 as one extra n-tile each).
constexpr int W2S = 1064;          // padded fp16 row stride
constexpr int XS  = 40;            // padded fp16 row stride for x tile
constexpr int SMEM_YTC = (32 * W2S + 64 * XS) * 2;

__global__ __launch_bounds__(256) void k_Y_tc(
    const float* __restrict__ x, const float* __restrict__ W2,
    const float* __restrict__ b2,
    __half* __restrict__ Yh, float* __restrict__ z, int rows)
{
    extern __shared__ __half smh[];
    __half* W2h = smh;             // [i=32][W2S]
    __half* xh  = smh + 32 * W2S;  // [64][XS]

    int tid = threadIdx.x, lane = tid & 31, w = tid >> 5;

    // Convert + PERMUTE W2 fp32 -> fp16 smem
    for (int idx = tid; idx < 8192; idx += 256) {
        float4 v = ((const float4*)W2)[idx];
        int g = idx * 4;
        int k = g >> 10, rem = g & 1023;
        int i = rem >> 5, o = rem & 31;
        __half2* dst = (__half2*)&W2h[i * W2S + k * 32 + o];
        dst[0] = __floats2half2_rn(v.x, v.y);
        dst[1] = __floats2half2_rn(v.z, v.w);
    }
    // b2 -> cols [1024,1056)
    {
        float4 vb = ((const float4*)b2)[tid];
        int g = tid * 4;
        int i = g >> 5, o = g & 31;
        __half2* dst = (__half2*)&W2h[i * W2S + 1024 + o];
        dst[0] = __floats2half2_rn(vb.x, vb.y);
        dst[1] = __floats2half2_rn(vb.z, vb.w);
    }
    // x tile -> fp16 smem (zero-padded)
    int n0 = blockIdx.x * 64;
    for (int i = tid; i < 64 * 32; i += 256) {
        int r = i >> 5, cc = i & 31;
        float v = (n0 + r < rows) ? x[(size_t)(n0 + r) * 32 + cc] : 0.f;
        xh[r * XS + cc] = __float2half_rn(v);
    }
    __syncthreads();

    // A fragments: 4 m-tiles x 2 k-steps
    uint32_t A[4][2][4];
    #pragma unroll
    for (int m = 0; m < 4; m++) {
        #pragma unroll
        for (int ks = 0; ks < 2; ks++) {
            uint32_t addr = smemu32(&xh[(m * 16 + (lane & 15)) * XS + ks * 16 + (lane >> 4) * 8]);
            asm volatile("ldmatrix.sync.aligned.m8n8.x4.shared.b16 {%0,%1,%2,%3}, [%4];"
                         : "=r"(A[m][ks][0]), "=r"(A[m][ks][1]),
                           "=r"(A[m][ks][2]), "=r"(A[m][ks][3])
                         : "r"(addr));
        }
    }

    int nb0 = w * 128;
    __half2* Y2 = (__half2*)Yh;
    #pragma unroll 4
    for (int n = 0; n < 16; n++) {
        int nb = nb0 + n * 8;
        uint32_t B[2][2];
        #pragma unroll
        for (int ks = 0; ks < 2; ks++) {
            uint32_t addr = smemu32(&W2h[(ks * 16 + (lane & 15)) * W2S + nb]);
            asm volatile("ldmatrix.sync.aligned.m8n8.x2.trans.shared.b16 {%0,%1}, [%2];"
                         : "=r"(B[ks][0]), "=r"(B[ks][1]) : "r"(addr));
        }
        #pragma unroll
        for (int m = 0; m < 4; m++) {
            float c0 = 0.f, c1 = 0.f, c2 = 0.f, c3 = 0.f;
            asm volatile(
                "mma.sync.aligned.m16n8k16.row.col.f32.f16.f16.f32 "
                "{%0,%1,%2,%3}, {%4,%5,%6,%7}, {%8,%9}, {%0,%1,%2,%3};"
                : "+f"(c0), "+f"(c1), "+f"(c2), "+f"(c3)
                : "r"(A[m][0][0]), "r"(A[m][0][1]), "r"(A[m][0][2]), "r"(A[m][0][3]),
                  "r"(B[0][0]), "r"(B[0][1]));
            asm volatile(
                "mma.sync.aligned.m16n8k16.row.col.f32.f16.f16.f32 "
                "{%0,%1,%2,%3}, {%4,%5,%6,%7}, {%8,%9}, {%0,%1,%2,%3};"
                : "+f"(c0), "+f"(c1), "+f"(c2), "+f"(c3)
                : "r"(A[m][1][0]), "r"(A[m][1][1]), "r"(A[m][1][2]), "r"(A[m][1][3]),
                  "r"(B[1][0]), "r"(B[1][1]));
            int r0 = n0 + m * 16 + (lane >> 2);
            int colh = (nb >> 1) + (lane & 3);
            if (r0 < rows)
                Y2[(size_t)r0 * 512 + colh] = __floats2half2_rn(c0, c1);
            if (r0 + 8 < rows)
                Y2[(size_t)(r0 + 8) * 512 + colh] = __floats2half2_rn(c2, c3);
        }
    }

    // z tile: warps 0..3, B cols [1024 + w*8, +8)
    if (w < 4) {
        int nb = 1024 + w * 8;
        uint32_t B[2][2];
        #pragma unroll
        for (int ks = 0; ks < 2; ks++) {
            uint32_t addr = smemu32(&W2h[(ks * 16 + (lane & 15)) * W2S + nb]);
            asm volatile("ldmatrix.sync.aligned.m8n8.x2.trans.shared.b16 {%0,%1}, [%2];"
                         : "=r"(B[ks][0]), "=r"(B[ks][1]) : "r"(addr));
        }
        #pragma unroll
        for (int m = 0; m < 4; m++) {
            float c0 = 0.f, c1 = 0.f, c2 = 0.f, c3 = 0.f;
            asm volatile(
                "mma.sync.aligned.m16n8k16.row.col.f32.f16.f16.f32 "
                "{%0,%1,%2,%3}, {%4,%5,%6,%7}, {%8,%9}, {%0,%1,%2,%3};"
                : "+f"(c0), "+f"(c1), "+f"(c2), "+f"(c3)
                : "r"(A[m][0][0]), "r"(A[m][0][1]), "r"(A[m][0][2]), "r"(A[m][0][3]),
                  "r"(B[0][0]), "r"(B[0][1]));
            asm volatile(
                "mma.sync.aligned.m16n8k16.row.col.f32.f16.f16.f32 "
                "{%0,%1,%2,%3}, {%4,%5,%6,%7}, {%8,%9}, {%0,%1,%2,%3};"
                : "+f"(c0), "+f"(c1), "+f"(c2), "+f"(c3)
                : "r"(A[m][1][0]), "r"(A[m][1][1]), "r"(A[m][1][2]), "r"(A[m][1][3]),
                  "r"(B[1][0]), "r"(B[1][1]));
            int r0 = n0 + m * 16 + (lane >> 2);
            int col = w * 8 + (lane & 3) * 2;
            if (r0 < rows)
                *(float2*)&z[(size_t)r0 * 32 + col] = make_float2(c0, c1);
            if (r0 + 8 < rows)
                *(float2*)&z[(size_t)(r0 + 8) * 32 + col] = make_float2(c2, c3);
        }
    }
}

// One warp per edge. Yh plain row-major. lane = p*16 + q handles o-pair
// (2q, 2q+1) over k in {p, p+2, ..., p+30}; shfl_xor(16) combines halves.
__global__ __launch_bounds__(256) void k_edge(
    const int* __restrict__ eidx, const float* __restrict__ ef,
    const float* __restrict__ w1, const float* __restrict__ b1,
    const __half* __restrict__ Yh, const float* __restrict__ z,
    float* __restrict__ agg, int ne)
{
    __shared__ float w1s[8 * 32];
    __shared__ float b1s[32];
    int tid = threadIdx.x;
    if (tid < 256) w1s[tid] = w1[tid];
    if (tid < 32)  b1s[tid] = b1[tid];
    __syncthreads();

    int lane = tid & 31;
    int e = blockIdx.x * 8 + (tid >> 5);
    if (e >= ne) return;

    int s = eidx[e];
    int d = eidx[ne + e];

    float h = b1s[lane];                    // h index = lane
    const float* efe = &ef[(size_t)e * 8];
    #pragma unroll
    for (int j = 0; j < 8; j++) h += efe[j] * w1s[j * 32 + lane];
    h = fmaxf(h, 0.f);

    int p = lane >> 4;                      // k parity
    float2 acc = make_float2(0.f, 0.f);
    const __half2* Yr2 = (const __half2*)&Yh[(size_t)s * 1024];
    #pragma unroll
    for (int it = 0; it < 16; it++) {
        int k = 2 * it + p;
        float hk = __shfl_sync(0xffffffffu, h, k);
        float2 v = __half22float2(Yr2[it * 32 + lane]);
        acc.x += hk * v.x;
        acc.y += hk * v.y;
    }
    acc.x += __shfl_xor_sync(0xffffffffu, acc.x, 16);
    acc.y += __shfl_xor_sync(0xffffffffu, acc.y, 16);

    int q = lane & 15;
    int o = 2 * q + p;
    float val = (p ? acc.y : acc.x) + z[(size_t)s * 32 + o];
    atomicAdd(&agg[(size_t)d * 32 + o], val);
}

// Fused: out = relu(agg/cnt + xin @ rw + rb) ; mout = out @ lw + lb
// Clears agg (consume-and-clear). One warp per row.
__global__ __launch_bounds__(256) void k_convlin(
    const float* __restrict__ xin, float* __restrict__ agg,
    const float* __restrict__ cnt,
    const float* __restrict__ rw, const float* __restrict__ rb,
    const float* __restrict__ lw, const float* __restrict__ lb,
    float* __restrict__ out, float* __restrict__ mout, int rows)
{
    __shared__ float rws[1024], lws[1024];
    __shared__ float rbs[32], lbs[32];
    int tid = threadIdx.x;
    for (int i = tid; i < 1024; i += 256) { rws[i] = rw[i]; lws[i] = lw[i]; }
    if (tid < 32) { rbs[tid] = rb[tid]; lbs[tid] = lb[tid]; }
    __syncthreads();

    int lane = tid & 31;
    int n = blockIdx.x * 8 + (tid >> 5);
    if (n >= rows) return;

    size_t base = (size_t)n * 32 + lane;
    float xr = xin[base];
    float acc = rbs[lane];
    #pragma unroll
    for (int i = 0; i < 32; i++)
        acc += __shfl_sync(0xffffffffu, xr, i) * rws[i * 32 + lane];
    float inv = 1.f / fmaxf(cnt[n], 1.f);
    acc += agg[base] * inv;
    agg[base] = 0.f;
    float o = fmaxf(acc, 0.f);
    out[base] = o;

    float macc = lbs[lane];
    #pragma unroll
    for (int i = 0; i < 32; i++)
        macc += __shfl_sync(0xffffffffu, o, i) * lws[i * 32 + lane];
    mout[base] = macc;
}

// One warp per assignment: agg[idx_out[a]] += m[idx_in[a]]
__global__ __launch_bounds__(256) void k_scatter(
    const int* __restrict__ idx_in, const int* __restrict__ idx_out,
    const float* __restrict__ m, float* __restrict__ agg, int n)
{
    int lane = threadIdx.x & 31;
    int a = blockIdx.x * 8 + (threadIdx.x >> 5);
    if (a >= n) return;
    atomicAdd(&agg[(size_t)idx_out[a] * 32 + lane],
              m[(size_t)idx_in[a] * 32 + lane]);
}

// out = base + agg/max(cnt,1); clears agg.
__global__ void k_resid(
    const float* __restrict__ base, float* __restrict__ agg,
    const float* __restrict__ cnt, float* __restrict__ out, int rows)
{
    int i = blockIdx.x * blockDim.x + threadIdx.x;
    if (i >= rows * 32) return;
    int n = i >> 5;
    out[i] = base[i] + agg[i] / fmaxf(cnt[n], 1.f);
    agg[i] = 0.f;
}

// ---------------------------------------------------------------------------
static inline int cdiv(int a, int b) { return (a + b - 1) / b; }

extern "C" void kernel_launch(void* const* d_in, const int* in_sizes, int n_in,
                              void* d_out, int out_size)
{
    const float* node_features   = (const float*)d_in[0];
    const int*   edge_index      = (const int*)d_in[1];
    const float* edge_features   = (const float*)d_in[2];
    const float* clique_features = (const float*)d_in[3];
    const int*   n2c_index       = (const int*)d_in[4];   // [2, A]: nid, cid
    const int*   cedge_index     = (const int*)d_in[5];
    const float* cedge_features  = (const float*)d_in[6];
    const float* nn1_w  = (const float*)d_in[7];
    const float* nn1_b  = (const float*)d_in[8];
    const float* nn2_w  = (const float*)d_in[9];
    const float* nn2_b  = (const float*)d_in[10];
    const float* root_w = (const float*)d_in[11];
    const float* root_b = (const float*)d_in[12];
    const float* n2c_w  = (const float*)d_in[13];
    const float* n2c_b  = (const float*)d_in[14];
    const float* cnn1_w = (const float*)d_in[15];
    const float* cnn1_b = (const float*)d_in[16];
    const float* cnn2_w = (const float*)d_in[17];
    const float* cnn2_b = (const float*)d_in[18];
    const float* croot_w = (const float*)d_in[19];
    const float* croot_b = (const float*)d_in[20];
    const float* c2n_w  = (const float*)d_in[21];
    const float* c2n_b  = (const float*)d_in[22];

    float *z, *x, *x2, *c, *c2, *agg, *m, *cntE, *cntCE, *cntAc, *cntAn;
    __half* Yh;
    cudaGetSymbolAddress((void**)&Yh, g_Yh);
    cudaGetSymbolAddress((void**)&z, g_z);
    cudaGetSymbolAddress((void**)&x, g_x);
    cudaGetSymbolAddress((void**)&x2, g_x2);
    cudaGetSymbolAddress((void**)&c, g_c);
    cudaGetSymbolAddress((void**)&c2, g_c2);
    cudaGetSymbolAddress((void**)&agg, g_agg);
    cudaGetSymbolAddress((void**)&m, g_m);
    cudaGetSymbolAddress((void**)&cntE, g_cntE);
    cudaGetSymbolAddress((void**)&cntCE, g_cntCE);
    cudaGetSymbolAddress((void**)&cntAc, g_cntAc);
    cudaGetSymbolAddress((void**)&cntAn, g_cntAn);

    float* out_x = (float*)d_out;                       // [N, H]
    float* out_c = (float*)d_out + (size_t)N_ * H_;     // [NC, H]

    cudaFuncSetAttribute(k_Y_tc, cudaFuncAttributeMaxDynamicSharedMemorySize, SMEM_YTC);

    k_zero_all<<<400, 256>>>(cntE, cntCE, cntAc, cntAn, agg);
    k_count_all<<<400, 256>>>(edge_index + E_, cedge_index + EC_,
                              n2c_index, n2c_index + A_,
                              cntE, cntCE, cntAc, cntAn);

    for (int l = 0; l < L_; l++) {
        const float* xin = (l == 0) ? node_features : x;
        const float* cin = (l == 0) ? clique_features : c;
        float* xout = (l == L_ - 1) ? out_x : x;
        float* cout = (l == L_ - 1) ? out_c : c;

        // ---- node NNConv + fused Node2Clique projection ----
        k_Y_tc<<<cdiv(N_, 64), 256, SMEM_YTC>>>(xin, nn2_w + (size_t)l * 32768,
                                                nn2_b + (size_t)l * 1024, Yh, z, N_);
        k_edge<<<cdiv(E_, 8), 256>>>(edge_index, edge_features,
                                     nn1_w + (size_t)l * 256, nn1_b + (size_t)l * 32,
                                     Yh, z, agg, E_);
        k_convlin<<<cdiv(N_, 8), 256>>>(xin, agg, cntE,
                                        root_w + (size_t)l * 1024, root_b + (size_t)l * 32,
                                        n2c_w + (size_t)l * 1024, n2c_b + (size_t)l * 32,
                                        x2, m, N_);
        k_scatter<<<cdiv(A_, 8), 256>>>(n2c_index, n2c_index + A_, m, agg, A_);
        k_resid<<<cdiv(NC_ * 32, 256), 256>>>(cin, agg, cntAc, c2, NC_);

        // ---- clique NNConv + fused Clique2Node projection ----
        k_Y_tc<<<cdiv(NC_, 64), 256, SMEM_YTC>>>(c2, cnn2_w + (size_t)l * 32768,
                                                 cnn2_b + (size_t)l * 1024, Yh, z, NC_);
        k_edge<<<cdiv(EC_, 8), 256>>>(cedge_index, cedge_features,
                                      cnn1_w + (size_t)l * 256, cnn1_b + (size_t)l * 32,
                                      Yh, z, agg, EC_);
        k_convlin<<<cdiv(NC_, 8), 256>>>(c2, agg, cntCE,
                                         croot_w + (size_t)l * 1024, croot_b + (size_t)l * 32,
                                         c2n_w + (size_t)l * 1024, c2n_b + (size_t)l * 32,
                                         cout, m, NC_);
        k_scatter<<<cdiv(A_, 8), 256>>>(n2c_index + A_, n2c_index, m, agg, A_);
        k_resid<<<cdiv(N_ * 32, 256), 256>>>(x2, agg, cntAn, xout, N_);
    }
}